// round 10
// baseline (speedup 1.0000x reference)
#include <cuda_runtime.h>
#include <cstdint>

#define B_  2
#define L_  4096
#define H_  8
#define D_  64
#define U_  45
#define BH_ (B_*H_)
#define NSPLIT_ 16
#define KCHUNK_ (L_/NSPLIT_)   // 256

// ---------------- device scratch (no allocations allowed) ----------------
__device__ int   g_idx[L_*U_];                  // 184320 sample indices
__device__ float g_M[BH_*L_];                   // sparsity measure
__device__ int   g_top[BH_*U_];                 // selected q per (bh, rank)
__device__ float g_qsel[BH_*U_*D_];             // selected Q rows, rank order
__device__ float g_scores[(size_t)BH_*U_*L_];   // 11.8 MB
__device__ float g_partial[NSPLIT_*BH_*U_*D_];  // 2.95 MB split-K partials

// ---------------- threefry2x32 (cipher verified vs Random123 vector) -----
__device__ __forceinline__ uint32_t rotl32(uint32_t x, int d) {
    return (x << d) | (x >> (32 - d));
}

__device__ __forceinline__ void threefry2x32(uint32_t k0, uint32_t k1,
                                             uint32_t x0, uint32_t x1,
                                             uint32_t& y0, uint32_t& y1) {
    uint32_t k2 = k0 ^ k1 ^ 0x1BD11BDAu;
    x0 += k0; x1 += k1;
#define RND(r) { x0 += x1; x1 = rotl32(x1, r); x1 ^= x0; }
    RND(13) RND(15) RND(26) RND(6)  x0 += k1; x1 += k2 + 1u;
    RND(17) RND(29) RND(16) RND(24) x0 += k2; x1 += k0 + 2u;
    RND(13) RND(15) RND(26) RND(6)  x0 += k0; x1 += k1 + 3u;
    RND(17) RND(29) RND(16) RND(24) x0 += k1; x1 += k2 + 4u;
    RND(13) RND(15) RND(26) RND(6)  x0 += k2; x1 += k0 + 5u;
#undef RND
    y0 = x0; y1 = x1;
}

// jax.random.randint(key(1), (L,U), 0, L), modern defaults:
//   k1, k2 = split(key)
//   higher = random_bits(k1), lower = random_bits(k2)
//   multiplier = (2^16 % 4096)^2 % 4096 = 0
//   idx = lower_bits % 4096            <-- k2, the SECOND subkey
// partitionable split:  k2 = threefry((0,1), ctr=(0,1))  (both words)
// partitionable bits32: ctr = (0, flat_j), out = bits1 ^ bits2
__global__ void k_idx() {
    int j = blockIdx.x * blockDim.x + threadIdx.x;
    if (j >= L_ * U_) return;
    uint32_t k2a, k2b;
    threefry2x32(0u, 1u, 0u, 1u, k2a, k2b);        // second subkey from split
    uint32_t z0, z1;
    threefry2x32(k2a, k2b, 0u, (uint32_t)j, z0, z1);
    g_idx[j] = (int)((z0 ^ z1) & (uint32_t)(L_ - 1));
}

// ---------------- M = max_s(QK_s) - sum_s(QK_s)/L ----------------
// one warp per (bh, q); lane holds 2 floats of the Q row
__global__ void k_M(const float* __restrict__ Q, const float* __restrict__ K) {
    int w = (blockIdx.x * blockDim.x + threadIdx.x) >> 5;
    int lane = threadIdx.x & 31;
    if (w >= BH_ * L_) return;
    int q  = w & (L_ - 1);
    int bh = w >> 12;
    int b = bh >> 3, h = bh & 7;

    const float2* qrow = (const float2*)(Q + ((b * L_ + q) * H_ + h) * D_);
    float2 qv = __ldg(qrow + lane);

    const int* idxp = g_idx + q * U_;
    // stage the 45 indices into 2 regs, broadcast via shfl
    int i0 = __ldg(idxp + lane);                              // s = lane (0..31)
    int i1 = (lane + 32 < U_) ? __ldg(idxp + lane + 32) : 0;  // s = lane+32 (32..44)

    const float* Kb = K + (b * L_ * H_ + h) * D_;

    int kidx0 = __shfl_sync(0xffffffffu, i0, 0);
    float2 kv = __ldg(((const float2*)(Kb + kidx0 * (H_ * D_))) + lane);

    float mx = -INFINITY, sm = 0.f;
#pragma unroll 1
    for (int s = 0; s < U_; s++) {
        float2 kvn = make_float2(0.f, 0.f);
        if (s + 1 < U_) {
            int sn = s + 1;
            int a   = __shfl_sync(0xffffffffu, i0, sn & 31);
            int bsh = __shfl_sync(0xffffffffu, i1, sn & 31);
            int kn = (sn < 32) ? a : bsh;
            kvn = __ldg(((const float2*)(Kb + kn * (H_ * D_))) + lane);
        }
        float p = qv.x * kv.x + qv.y * kv.y;
#pragma unroll
        for (int o = 16; o; o >>= 1) p += __shfl_xor_sync(0xffffffffu, p, o);
        mx = fmaxf(mx, p);
        sm += p;
        kv = kvn;
    }
    if (lane == 0) g_M[bh * L_ + q] = mx - sm * (1.0f / (float)L_);
}

// ---------------- top-45 selection (lowest-index tie-break, rank order) ---
__global__ void k_topk(const float* __restrict__ Q) {
    __shared__ float sM[L_];
    __shared__ float swv[8];
    __shared__ int   swi[8];
    __shared__ int   ssel[U_];
    int bh = blockIdx.x;
    int tid = threadIdx.x;
    int b = bh >> 3, h = bh & 7;

    for (int i = tid; i < L_; i += 256) sM[i] = g_M[bh * L_ + i];
    __syncthreads();

    for (int it = 0; it < U_; it++) {
        float bv = -INFINITY;
        int bi = -1;
        for (int i = tid; i < L_; i += 256) {
            float v = sM[i];
            if (v > bv || (v == bv && (unsigned)i < (unsigned)bi)) { bv = v; bi = i; }
        }
#pragma unroll
        for (int o = 16; o; o >>= 1) {
            float ov = __shfl_xor_sync(0xffffffffu, bv, o);
            int   oi = __shfl_xor_sync(0xffffffffu, bi, o);
            if (ov > bv || (ov == bv && (unsigned)oi < (unsigned)bi)) { bv = ov; bi = oi; }
        }
        if ((tid & 31) == 0) { swv[tid >> 5] = bv; swi[tid >> 5] = bi; }
        __syncthreads();
        if (tid < 32) {
            float v2 = (tid < 8) ? swv[tid] : -INFINITY;
            int   i2 = (tid < 8) ? swi[tid] : -1;
#pragma unroll
            for (int o = 4; o; o >>= 1) {
                float ov = __shfl_xor_sync(0xffffffffu, v2, o);
                int   oi = __shfl_xor_sync(0xffffffffu, i2, o);
                if (ov > v2 || (ov == v2 && (unsigned)oi < (unsigned)i2)) { v2 = ov; i2 = oi; }
            }
            if (tid == 0) {
                g_top[bh * U_ + it] = i2;
                ssel[it] = i2;
                sM[i2] = -INFINITY;
            }
        }
        __syncthreads();
    }
    // copy selected Q rows in rank order
    for (int t = tid; t < U_ * D_; t += 256) {
        int r = t >> 6, d = t & 63;
        g_qsel[(bh * U_ + r) * D_ + d] = Q[((b * L_ + ssel[r]) * H_ + h) * D_ + d];
    }
}

// ---------------- scores = (Qsel @ K^T) * scale, masked ----------------
// grid (16 key-tiles, BH); thread per key, K row in regs, Q broadcast smem
__global__ void k_scores(const float* __restrict__ K, const int* __restrict__ mask) {
    __shared__ float4 sQ[U_][D_ / 4];   // 11.5 KB
    int bh = blockIdx.y;
    int b = bh >> 3, h = bh & 7;
    int tid = threadIdx.x;

    for (int t = tid; t < U_ * (D_ / 4); t += 256)
        sQ[t >> 4][t & 15] = ((const float4*)g_qsel)[bh * U_ * (D_ / 4) + t];
    __syncthreads();

    int k = blockIdx.x * 256 + tid;
    const float4* krow = (const float4*)(K + ((b * L_ + k) * H_ + h) * D_);
    float4 kr[16];
#pragma unroll
    for (int i = 0; i < 16; i++) kr[i] = __ldg(krow + i);
    int m = __ldg(mask + b * L_ + k);
    const float scale = 0.125f;   // 1/sqrt(64)

    for (int uc = 0; uc < U_; uc += 5) {
        float acc[5] = {0.f, 0.f, 0.f, 0.f, 0.f};
#pragma unroll
        for (int d4 = 0; d4 < 16; d4++) {
            float4 kv = kr[d4];
#pragma unroll
            for (int j = 0; j < 5; j++) {
                float4 qv = sQ[uc + j][d4];
                acc[j] += qv.x * kv.x + qv.y * kv.y + qv.z * kv.z + qv.w * kv.w;
            }
        }
#pragma unroll
        for (int j = 0; j < 5; j++) {
            float s = (m == 0) ? -INFINITY : acc[j] * scale;
            g_scores[((size_t)bh * U_ + uc + j) * L_ + k] = s;
        }
    }
}

// ---------------- row softmax over 4096 ----------------
__global__ void k_softmax() {
    int row = blockIdx.x;   // bh*U + u
    float* p = g_scores + (size_t)row * L_;
    int tid = threadIdx.x;
    __shared__ float sred[8];
    __shared__ float sbc;

    float4 v[4];
    float mx = -INFINITY;
#pragma unroll
    for (int i = 0; i < 4; i++) {
        v[i] = ((const float4*)p)[tid + i * 256];
        mx = fmaxf(mx, fmaxf(fmaxf(v[i].x, v[i].y), fmaxf(v[i].z, v[i].w)));
    }
#pragma unroll
    for (int o = 16; o; o >>= 1) mx = fmaxf(mx, __shfl_xor_sync(0xffffffffu, mx, o));
    if ((tid & 31) == 0) sred[tid >> 5] = mx;
    __syncthreads();
    if (tid < 32) {
        float m2 = (tid < 8) ? sred[tid] : -INFINITY;
#pragma unroll
        for (int o = 4; o; o >>= 1) m2 = fmaxf(m2, __shfl_xor_sync(0xffffffffu, m2, o));
        if (tid == 0) sbc = m2;
    }
    __syncthreads();
    mx = sbc;

    float sm = 0.f;
#pragma unroll
    for (int i = 0; i < 4; i++) {
        v[i].x = expf(v[i].x - mx); v[i].y = expf(v[i].y - mx);
        v[i].z = expf(v[i].z - mx); v[i].w = expf(v[i].w - mx);
        sm += v[i].x + v[i].y + v[i].z + v[i].w;
    }
#pragma unroll
    for (int o = 16; o; o >>= 1) sm += __shfl_xor_sync(0xffffffffu, sm, o);
    __syncthreads();
    if ((tid & 31) == 0) sred[tid >> 5] = sm;
    __syncthreads();
    if (tid < 32) {
        float s2 = (tid < 8) ? sred[tid] : 0.f;
#pragma unroll
        for (int o = 4; o; o >>= 1) s2 += __shfl_xor_sync(0xffffffffu, s2, o);
        if (tid == 0) sbc = s2;
    }
    __syncthreads();
    float inv = 1.0f / sbc;
#pragma unroll
    for (int i = 0; i < 4; i++) {
        v[i].x *= inv; v[i].y *= inv; v[i].z *= inv; v[i].w *= inv;
        ((float4*)p)[tid + i * 256] = v[i];
    }
}

// ---------------- context = A @ V, split-K partials ----------------
// grid (NSPLIT, BH); 512 threads: g = tid/64 selects u-subset, d = tid%64
__global__ void k_ctx(const float* __restrict__ V) {
    int bh = blockIdx.y;
    int b = bh >> 3, h = bh & 7;
    int ks = blockIdx.x;
    int tid = threadIdx.x;
    int g = tid >> 6, d = tid & 63;
    int nu = (g < 5) ? 6 : 5;   // u = g, g+8, ... < 45

    float acc[6] = {0.f, 0.f, 0.f, 0.f, 0.f, 0.f};
    int k0 = ks * KCHUNK_;
    const float* Vb = V + (b * L_ * H_ + h) * D_ + d;

    for (int kk = 0; kk < KCHUNK_; kk += 2) {
        int k = k0 + kk;
        float vv0 = __ldg(Vb + (size_t)k * (H_ * D_));
        float vv1 = __ldg(Vb + (size_t)(k + 1) * (H_ * D_));
#pragma unroll
        for (int j = 0; j < 6; j++) {
            if (j < nu) {
                int u = g + 8 * j;
                float2 a = __ldg((const float2*)(g_scores + ((size_t)bh * U_ + u) * L_ + k));
                acc[j] += a.x * vv0 + a.y * vv1;
            }
        }
    }
    for (int j = 0; j < nu; j++) {
        int u = g + 8 * j;
        g_partial[((ks * BH_ + bh) * U_ + u) * D_ + d] = acc[j];
    }
}

// ---------------- reduce partials, write (b, rank, h, d) ----------------
__global__ void k_out(float* __restrict__ out) {
    int i = blockIdx.x * 256 + threadIdx.x;
    if (i >= BH_ * U_ * D_) return;
    float s = 0.f;
#pragma unroll
    for (int ks = 0; ks < NSPLIT_; ks++) s += g_partial[ks * (BH_ * U_ * D_) + i];
    int d = i & 63;
    int rest = i >> 6;
    int u = rest % U_;
    int bh = rest / U_;
    int b = bh >> 3, h = bh & 7;
    out[((b * U_ + u) * H_ + h) * D_ + d] = s;
}

// ---------------- launch ----------------
extern "C" void kernel_launch(void* const* d_in, const int* in_sizes, int n_in,
                              void* d_out, int out_size) {
    const float* Q    = (const float*)d_in[0];
    const float* K    = (const float*)d_in[1];
    const float* V    = (const float*)d_in[2];
    const int*   mask = (const int*)d_in[3];
    float* out = (float*)d_out;

    k_idx<<<(L_ * U_ + 255) / 256, 256>>>();
    k_M<<<(BH_ * L_ * 32) / 256, 256>>>(Q, K);
    k_topk<<<BH_, 256>>>(Q);
    k_scores<<<dim3(L_ / 256, BH_), 256>>>(K, mask);
    k_softmax<<<BH_ * U_, 256>>>();
    k_ctx<<<dim3(NSPLIT_, BH_), 512>>>(V);
    k_out<<<(BH_ * U_ * D_ + 255) / 256, 256>>>(out);
}

// round 11
// speedup vs baseline: 1.3660x; 1.3660x over previous
#include <cuda_runtime.h>
#include <cstdint>

#define B_  2
#define L_  4096
#define H_  8
#define D_  64
#define U_  45
#define BH_ (B_*H_)
#define NSPLIT_ 32
#define KCHUNK_ (L_/NSPLIT_)   // 128

// ---------------- device scratch (no allocations allowed) ----------------
__device__ int   g_idx[L_*U_];                  // 184320 sample indices
__device__ float g_M[BH_*L_];                   // sparsity measure
__device__ int   g_top[BH_*U_];                 // selected q per (bh, rank)
__device__ float g_qsel[BH_*U_*D_];             // selected Q rows, rank order
__device__ float g_scores[(size_t)BH_*U_*L_];   // 11.8 MB
__device__ float g_partial[NSPLIT_*BH_*U_*D_];  // 5.9 MB split-K partials

// ---------------- threefry2x32 (verified vs Random123 vector) ------------
__device__ __forceinline__ uint32_t rotl32(uint32_t x, int d) {
    return (x << d) | (x >> (32 - d));
}

__device__ __forceinline__ void threefry2x32(uint32_t k0, uint32_t k1,
                                             uint32_t x0, uint32_t x1,
                                             uint32_t& y0, uint32_t& y1) {
    uint32_t k2 = k0 ^ k1 ^ 0x1BD11BDAu;
    x0 += k0; x1 += k1;
#define RND(r) { x0 += x1; x1 = rotl32(x1, r); x1 ^= x0; }
    RND(13) RND(15) RND(26) RND(6)  x0 += k1; x1 += k2 + 1u;
    RND(17) RND(29) RND(16) RND(24) x0 += k2; x1 += k0 + 2u;
    RND(13) RND(15) RND(26) RND(6)  x0 += k0; x1 += k1 + 3u;
    RND(17) RND(29) RND(16) RND(24) x0 += k1; x1 += k2 + 4u;
    RND(13) RND(15) RND(26) RND(6)  x0 += k2; x1 += k0 + 5u;
#undef RND
    y0 = x0; y1 = x1;
}

// randint(key(1),(L,U),0,L): k1,k2 = split(key); idx = lower_bits(k2) & 4095
// partitionable split: k2 = threefry((0,1), (0,1)); bits: ctr (0,j), y0^y1.
__global__ void k_idx() {
    int j = blockIdx.x * blockDim.x + threadIdx.x;
    if (j >= L_ * U_) return;
    uint32_t k2a, k2b;
    threefry2x32(0u, 1u, 0u, 1u, k2a, k2b);
    uint32_t z0, z1;
    threefry2x32(k2a, k2b, 0u, (uint32_t)j, z0, z1);
    g_idx[j] = (int)((z0 ^ z1) & (uint32_t)(L_ - 1));
}

// ---------------- M = max_s(QK_s) - sum_s(QK_s)/L ----------------
// one warp per (bh,q); two samples per iteration (one per half-warp),
// 16 lanes x float4 = 64-float K row, 4-stage shfl reduce, depth-1 prefetch
__global__ void k_M(const float* __restrict__ Q, const float* __restrict__ K) {
    int w = (blockIdx.x * blockDim.x + threadIdx.x) >> 5;
    int lane = threadIdx.x & 31;
    if (w >= BH_ * L_) return;
    int q  = w & (L_ - 1);
    int bh = w >> 12;
    int b = bh >> 3, h = bh & 7;
    int half = lane >> 4;
    int lpos = lane & 15;

    const float4* qrow = (const float4*)(Q + ((b * L_ + q) * H_ + h) * D_);
    float4 qv = __ldg(qrow + lpos);

    const int* idxp = g_idx + q * U_;
    int i0 = __ldg(idxp + lane);                               // s = 0..31
    int i1 = (lane + 32 < U_) ? __ldg(idxp + lane + 32) : 0;   // s = 32..44

    const float* Kb = K + (b * L_ * H_ + h) * D_;

    // fetch row index for sample s (s may differ per half-warp)
#define FETCH_ROW(sv, rv) {                                   \
        int sc_ = (sv) & 31;                                  \
        int a_  = __shfl_sync(0xffffffffu, i0, sc_);          \
        int c_  = __shfl_sync(0xffffffffu, i1, sc_);          \
        rv = ((sv) < 32) ? a_ : c_; }

    int s0 = half;
    int r0; FETCH_ROW(s0, r0);
    float4 kv = __ldg(((const float4*)(Kb + r0 * (H_ * D_))) + lpos);

    float mx = -INFINITY, sm = 0.f;
#pragma unroll 1
    for (int t = 0; t < 23; t++) {
        int s = 2 * t + half;
        float4 kvn = make_float4(0.f, 0.f, 0.f, 0.f);
        if (t < 22) {
            int sn = 2 * (t + 1) + half;
            if (sn > 44) sn = 44;           // clamp (only half=1, t=21..)
            int rn; FETCH_ROW(sn, rn);
            kvn = __ldg(((const float4*)(Kb + rn * (H_ * D_))) + lpos);
        }
        float p = qv.x * kv.x + qv.y * kv.y + qv.z * kv.z + qv.w * kv.w;
        p += __shfl_xor_sync(0xffffffffu, p, 8);
        p += __shfl_xor_sync(0xffffffffu, p, 4);
        p += __shfl_xor_sync(0xffffffffu, p, 2);
        p += __shfl_xor_sync(0xffffffffu, p, 1);
        if (s < U_) { mx = fmaxf(mx, p); sm += p; }
        kv = kvn;
    }
#undef FETCH_ROW
    // combine the two halves
    float omx = __shfl_xor_sync(0xffffffffu, mx, 16);
    float osm = __shfl_xor_sync(0xffffffffu, sm, 16);
    mx = fmaxf(mx, omx);
    sm += osm;
    if (lane == 0) g_M[bh * L_ + q] = mx - sm * (1.0f / (float)L_);
}

// ---------------- top-45 selection (lowest-index tie-break, rank order) ---
__global__ void k_topk(const float* __restrict__ Q) {
    __shared__ float sM[L_];
    __shared__ float swv[16];
    __shared__ int   swi[16];
    __shared__ int   ssel[U_];
    int bh = blockIdx.x;
    int tid = threadIdx.x;          // 512 threads
    int b = bh >> 3, h = bh & 7;

    for (int i = tid; i < L_; i += 512) sM[i] = g_M[bh * L_ + i];
    __syncthreads();

    for (int it = 0; it < U_; it++) {
        float bv = -INFINITY;
        int bi = -1;
        for (int i = tid; i < L_; i += 512) {
            float v = sM[i];
            if (v > bv || (v == bv && (unsigned)i < (unsigned)bi)) { bv = v; bi = i; }
        }
#pragma unroll
        for (int o = 16; o; o >>= 1) {
            float ov = __shfl_xor_sync(0xffffffffu, bv, o);
            int   oi = __shfl_xor_sync(0xffffffffu, bi, o);
            if (ov > bv || (ov == bv && (unsigned)oi < (unsigned)bi)) { bv = ov; bi = oi; }
        }
        if ((tid & 31) == 0) { swv[tid >> 5] = bv; swi[tid >> 5] = bi; }
        __syncthreads();
        if (tid < 32) {
            float v2 = (tid < 16) ? swv[tid] : -INFINITY;
            int   i2 = (tid < 16) ? swi[tid] : -1;
#pragma unroll
            for (int o = 8; o; o >>= 1) {
                float ov = __shfl_xor_sync(0xffffffffu, v2, o);
                int   oi = __shfl_xor_sync(0xffffffffu, i2, o);
                if (ov > v2 || (ov == v2 && (unsigned)oi < (unsigned)i2)) { v2 = ov; i2 = oi; }
            }
            if (tid == 0) {
                g_top[bh * U_ + it] = i2;
                ssel[it] = i2;
                sM[i2] = -INFINITY;
            }
        }
        __syncthreads();
    }
    // copy selected Q rows in rank order
    for (int t = tid; t < U_ * D_; t += 512) {
        int r = t >> 6, d = t & 63;
        g_qsel[(bh * U_ + r) * D_ + d] = Q[((b * L_ + ssel[r]) * H_ + h) * D_ + d];
    }
}

// ---------------- scores = (Qsel @ K^T) * scale, masked ----------------
// grid (16 key-tiles, BH); thread per key, K row in regs, Q broadcast smem
__global__ void k_scores(const float* __restrict__ K, const int* __restrict__ mask) {
    __shared__ float4 sQ[U_][D_ / 4];   // 11.5 KB
    int bh = blockIdx.y;
    int b = bh >> 3, h = bh & 7;
    int tid = threadIdx.x;

    for (int t = tid; t < U_ * (D_ / 4); t += 256)
        sQ[t >> 4][t & 15] = ((const float4*)g_qsel)[bh * U_ * (D_ / 4) + t];
    __syncthreads();

    int k = blockIdx.x * 256 + tid;
    const float4* krow = (const float4*)(K + ((b * L_ + k) * H_ + h) * D_);
    float4 kr[16];
#pragma unroll
    for (int i = 0; i < 16; i++) kr[i] = __ldg(krow + i);
    int m = __ldg(mask + b * L_ + k);
    const float scale = 0.125f;   // 1/sqrt(64)

    for (int uc = 0; uc < U_; uc += 5) {
        float acc[5] = {0.f, 0.f, 0.f, 0.f, 0.f};
#pragma unroll
        for (int d4 = 0; d4 < 16; d4++) {
            float4 kv = kr[d4];
#pragma unroll
            for (int j = 0; j < 5; j++) {
                float4 qv = sQ[uc + j][d4];
                acc[j] += qv.x * kv.x + qv.y * kv.y + qv.z * kv.z + qv.w * kv.w;
            }
        }
#pragma unroll
        for (int j = 0; j < 5; j++) {
            float s = (m == 0) ? -INFINITY : acc[j] * scale;
            g_scores[((size_t)bh * U_ + uc + j) * L_ + k] = s;
        }
    }
}

// ---------------- row softmax over 4096 ----------------
__global__ void k_softmax() {
    int row = blockIdx.x;   // bh*U + u
    float* p = g_scores + (size_t)row * L_;
    int tid = threadIdx.x;
    __shared__ float sred[8];
    __shared__ float sbc;

    float4 v[4];
    float mx = -INFINITY;
#pragma unroll
    for (int i = 0; i < 4; i++) {
        v[i] = ((const float4*)p)[tid + i * 256];
        mx = fmaxf(mx, fmaxf(fmaxf(v[i].x, v[i].y), fmaxf(v[i].z, v[i].w)));
    }
#pragma unroll
    for (int o = 16; o; o >>= 1) mx = fmaxf(mx, __shfl_xor_sync(0xffffffffu, mx, o));
    if ((tid & 31) == 0) sred[tid >> 5] = mx;
    __syncthreads();
    if (tid < 32) {
        float m2 = (tid < 8) ? sred[tid] : -INFINITY;
#pragma unroll
        for (int o = 4; o; o >>= 1) m2 = fmaxf(m2, __shfl_xor_sync(0xffffffffu, m2, o));
        if (tid == 0) sbc = m2;
    }
    __syncthreads();
    mx = sbc;

    float sm = 0.f;
#pragma unroll
    for (int i = 0; i < 4; i++) {
        v[i].x = expf(v[i].x - mx); v[i].y = expf(v[i].y - mx);
        v[i].z = expf(v[i].z - mx); v[i].w = expf(v[i].w - mx);
        sm += v[i].x + v[i].y + v[i].z + v[i].w;
    }
#pragma unroll
    for (int o = 16; o; o >>= 1) sm += __shfl_xor_sync(0xffffffffu, sm, o);
    __syncthreads();
    if ((tid & 31) == 0) sred[tid >> 5] = sm;
    __syncthreads();
    if (tid < 32) {
        float s2 = (tid < 8) ? sred[tid] : 0.f;
#pragma unroll
        for (int o = 4; o; o >>= 1) s2 += __shfl_xor_sync(0xffffffffu, s2, o);
        if (tid == 0) sbc = s2;
    }
    __syncthreads();
    float inv = 1.0f / sbc;
#pragma unroll
    for (int i = 0; i < 4; i++) {
        v[i].x *= inv; v[i].y *= inv; v[i].z *= inv; v[i].w *= inv;
        ((float4*)p)[tid + i * 256] = v[i];
    }
}

// ---------------- context = A @ V, split-K partials ----------------
// grid (NSPLIT, BH); 512 threads: g = tid/64 selects u-subset, d = tid%64
// float4 A loads: per 4-k step only 4 V LDG.32 + <=6 A LDG.128
__global__ void k_ctx(const float* __restrict__ V) {
    int bh = blockIdx.y;
    int b = bh >> 3, h = bh & 7;
    int ks = blockIdx.x;
    int tid = threadIdx.x;
    int g = tid >> 6, d = tid & 63;
    int nu = (g < 5) ? 6 : 5;   // u = g, g+8, ... < 45

    float acc[6] = {0.f, 0.f, 0.f, 0.f, 0.f, 0.f};
    int k0 = ks * KCHUNK_;
    const float* Vb = V + (b * L_ * H_ + h) * D_ + d;

    for (int kk = 0; kk < KCHUNK_; kk += 4) {
        int k = k0 + kk;
        float vv0 = __ldg(Vb + (size_t)(k + 0) * (H_ * D_));
        float vv1 = __ldg(Vb + (size_t)(k + 1) * (H_ * D_));
        float vv2 = __ldg(Vb + (size_t)(k + 2) * (H_ * D_));
        float vv3 = __ldg(Vb + (size_t)(k + 3) * (H_ * D_));
#pragma unroll
        for (int j = 0; j < 6; j++) {
            if (j < nu) {
                int u = g + 8 * j;
                float4 a = __ldg((const float4*)(g_scores + ((size_t)bh * U_ + u) * L_ + k));
                acc[j] += a.x * vv0 + a.y * vv1 + a.z * vv2 + a.w * vv3;
            }
        }
    }
    for (int j = 0; j < nu; j++) {
        int u = g + 8 * j;
        g_partial[((ks * BH_ + bh) * U_ + u) * D_ + d] = acc[j];
    }
}

// ---------------- reduce partials, write (b, rank, h, d) ----------------
__global__ void k_out(float* __restrict__ out) {
    int i = blockIdx.x * 256 + threadIdx.x;
    if (i >= BH_ * U_ * D_) return;
    float s = 0.f;
#pragma unroll
    for (int ks = 0; ks < NSPLIT_; ks++) s += g_partial[ks * (BH_ * U_ * D_) + i];
    int d = i & 63;
    int rest = i >> 6;
    int u = rest % U_;
    int bh = rest / U_;
    int b = bh >> 3, h = bh & 7;
    out[((b * U_ + u) * H_ + h) * D_ + d] = s;
}

// ---------------- launch ----------------
extern "C" void kernel_launch(void* const* d_in, const int* in_sizes, int n_in,
                              void* d_out, int out_size) {
    const float* Q    = (const float*)d_in[0];
    const float* K    = (const float*)d_in[1];
    const float* V    = (const float*)d_in[2];
    const int*   mask = (const int*)d_in[3];
    float* out = (float*)d_out;

    k_idx<<<(L_ * U_ + 255) / 256, 256>>>();
    k_M<<<(BH_ * L_ * 32) / 256, 256>>>(Q, K);
    k_topk<<<BH_, 512>>>(Q);
    k_scores<<<dim3(L_ / 256, BH_), 256>>>(K, mask);
    k_softmax<<<BH_ * U_, 256>>>();
    k_ctx<<<dim3(NSPLIT_, BH_), 512>>>(V);
    k_out<<<(BH_ * U_ * D_ + 255) / 256, 256>>>(out);
}